// round 14
// baseline (speedup 1.0000x reference)
#include <cuda_runtime.h>
#include <cuda_fp16.h>
#include <math.h>

#define Bb 4
#define Gg 128
#define Nn 2048
#define Pp 4
#define Ff 64
#define BP 16
#define ZTOL 1e-9f
#define NCH 128
#define CHR 16
#define MAXNNZ (1 << 19)
#define MAXE 256

__device__ __align__(16) __half2 g_Wxh[BP * Nn * (Ff / 2)];
__device__ __align__(16) float4  g_T1n[Nn * BP + BP];
__device__ __align__(16) float4  g_T2n[Nn * BP];
__device__ float g_s2p[BP * Nn];
__device__ __align__(16) int g_cnt[Nn * NCH];
__device__ __align__(16) int g_off2[Nn * NCH];
__device__ int   g_tot[Nn];
__device__ int   g_colptr[Nn + 1];
__device__ __align__(16) float2 g_rv[MAXNNZ];
__device__ __align__(16) float2 g_sc[(size_t)Nn * NCH * 16]; // slot scratch 33.5MB
__device__ __align__(16) float  g_yT[BP * Nn * Ff];          // [bp][n][f] 8MB

// ---------------------------------------------------------------------------
// K1: Wx = W @ x per (b,p) -> fp16; s2 plane + T1 exp table.
// ---------------------------------------------------------------------------
__global__ void k1_wx(const float* __restrict__ x, const float* __restrict__ a,
                      const float* __restrict__ W) {
    const int b = blockIdx.z, p = blockIdx.y;
    const int n = blockIdx.x * 256 + threadIdx.x;

    __shared__ __align__(16) float Ws[Gg * Ff];
    __shared__ float as[2 * Ff];

    for (int i = threadIdx.x; i < Gg * Ff; i += 256) {
        int f = i >> 7, g = i & 127;
        Ws[g * Ff + f] = W[(p * Ff + f) * Gg + g];
    }
    if (threadIdx.x < 2 * Ff) as[threadIdx.x] = a[p * 2 * Ff + threadIdx.x];
    __syncthreads();

    float4 acc[16];
#pragma unroll
    for (int i = 0; i < 16; i++) acc[i] = make_float4(0.f, 0.f, 0.f, 0.f);

    const float* xb = x + ((size_t)b * Gg) * Nn + n;
    const float4* Ws4 = (const float4*)Ws;

    for (int g = 0; g < Gg; g++) {
        float xv = xb[(size_t)g * Nn];
#pragma unroll
        for (int i = 0; i < 16; i++) {
            float4 w = Ws4[g * 16 + i];
            acc[i].x += w.x * xv; acc[i].y += w.y * xv;
            acc[i].z += w.z * xv; acc[i].w += w.w * xv;
        }
    }

    const int bp = b * Pp + p;
    __half2* dsth = g_Wxh + (size_t)(bp * Nn + n) * (Ff / 2);
    float s1 = 0.f, s2 = 0.f;
#pragma unroll
    for (int i = 0; i < 16; i++) {
        dsth[2 * i]     = __floats2half2_rn(acc[i].x, acc[i].y);
        dsth[2 * i + 1] = __floats2half2_rn(acc[i].z, acc[i].w);
        s1 += as[4*i+0]*acc[i].x + as[4*i+1]*acc[i].y + as[4*i+2]*acc[i].z + as[4*i+3]*acc[i].w;
        s2 += as[Ff+4*i+0]*acc[i].x + as[Ff+4*i+1]*acc[i].y + as[Ff+4*i+2]*acc[i].z + as[Ff+4*i+3]*acc[i].w;
    }
    g_s2p[bp * Nn + n] = s2;
    g_T1n[n * BP + bp] = make_float4(s1, __expf(s1), __expf(0.2f * s1), 0.f);
}

// ---------------------------------------------------------------------------
// K2: ballot-compressed denominators (MUFU-free hot loop via T1 table).
// ---------------------------------------------------------------------------
__global__ void k2_rowstats(const float* __restrict__ S) {
    const int m = blockIdx.x;
    const int tid = threadIdx.x;
    const int w = tid >> 5, lane = tid & 31;

    __shared__ float red[8][BP];

    const float s2l = g_s2p[(lane & 15) * Nn + m];
    const float eas = __expf(s2l);
    const float ebs = __expf(0.2f * s2l);
    float D = 0.f;
    const float4* row4 = (const float4*)(S + (size_t)m * Nn);

#pragma unroll
    for (int seg = 0; seg < 2; seg++) {
        const int base = (seg * 8 + w) * 128;
        float4 v = row4[base / 4 + lane];
        int dn = m - (base + 4 * lane);
        if (dn == 0) v.x += 1.f; else if (dn == 1) v.y += 1.f;
        else if (dn == 2) v.z += 1.f; else if (dn == 3) v.w += 1.f;
        unsigned bm[4];
        bm[0] = __ballot_sync(0xffffffffu, fabsf(v.x) > ZTOL);
        bm[1] = __ballot_sync(0xffffffffu, fabsf(v.y) > ZTOL);
        bm[2] = __ballot_sync(0xffffffffu, fabsf(v.z) > ZTOL);
        bm[3] = __ballot_sync(0xffffffffu, fabsf(v.w) > ZTOL);
#pragma unroll
        for (int k = 0; k < 4; k++) {
            unsigned msk = bm[k];
            while (msk) {
                int j = __ffs(msk) - 1;
                msk &= msk - 1;
                int ne = base + 4 * j + k;
                float4 t1 = g_T1n[ne * BP + lane];
                float t = s2l + t1.x;
                D += (t >= 0.f) ? eas * t1.y : ebs * t1.z;
            }
        }
    }

    if (lane < BP) red[w][lane] = D;
    __syncthreads();
    if (tid < BP) {
        float d = 0.f;
#pragma unroll
        for (int ww = 0; ww < 8; ww++) d += red[ww][tid];
        float ci = (d > 0.f) ? 1.f / d : 0.f;
        float s2 = g_s2p[tid * Nn + m];
        g_T2n[m * BP + tid] =
            make_float4(s2, __expf(s2) * ci, __expf(0.2f * s2) * ci, 0.f);
    }
}

// ---------------------------------------------------------------------------
// K3: deterministic CSC build — SINGLE pass over S.
// k3_count: counts AND writes compacted entries into slot scratch.
// ---------------------------------------------------------------------------
__global__ void k3_count(const float* __restrict__ S) {
    const int cg = blockIdx.x * 256 + threadIdx.x;
    const int n0 = cg * 4;
    const int mc = blockIdx.y, m0 = mc * CHR;
    float2* sc0 = g_sc + ((size_t)(n0 + 0) * NCH + mc) * 16;
    float2* sc1 = g_sc + ((size_t)(n0 + 1) * NCH + mc) * 16;
    float2* sc2 = g_sc + ((size_t)(n0 + 2) * NCH + mc) * 16;
    float2* sc3 = g_sc + ((size_t)(n0 + 3) * NCH + mc) * 16;
    int c0 = 0, c1 = 0, c2 = 0, c3 = 0;
#pragma unroll
    for (int mm = 0; mm < CHR; mm++) {
        const int m = m0 + mm;
        float4 v = *(const float4*)(S + (size_t)m * Nn + n0);
        float mo = __int_as_float(m * (Ff / 2));
        if (fabsf(v.x) > ZTOL) sc0[c0++] = make_float2(mo, v.x);
        if (fabsf(v.y) > ZTOL) sc1[c1++] = make_float2(mo, v.y);
        if (fabsf(v.z) > ZTOL) sc2[c2++] = make_float2(mo, v.z);
        if (fabsf(v.w) > ZTOL) sc3[c3++] = make_float2(mo, v.w);
    }
    g_cnt[(n0 + 0) * NCH + mc] = c0;
    g_cnt[(n0 + 1) * NCH + mc] = c1;
    g_cnt[(n0 + 2) * NCH + mc] = c2;
    g_cnt[(n0 + 3) * NCH + mc] = c3;
}

__global__ void k3_offs() {   // warp per column: int4 per lane, shuffle scan
    const int n = blockIdx.x * 8 + (threadIdx.x >> 5);
    const int lane = threadIdx.x & 31;
    int4 c = *(const int4*)&g_cnt[n * NCH + 4 * lane];
    int s = c.x + c.y + c.z + c.w;
    int v = s;
#pragma unroll
    for (int off = 1; off < 32; off <<= 1) {
        int u = __shfl_up_sync(0xffffffffu, v, off);
        if (lane >= off) v += u;
    }
    int e = v - s;
    *(int4*)&g_off2[n * NCH + 4 * lane] =
        make_int4(e, e + c.x, e + c.x + c.y, e + c.x + c.y + c.z);
    if (lane == 31) g_tot[n] = v;
}

__global__ void k3_scan() {   // two-level shuffle scan: colptr over 2048 totals
    __shared__ int wsum[32];
    __shared__ int woff[32];
    const int tid = threadIdx.x;
    const int w = tid >> 5, lane = tid & 31;
    int a = g_tot[2 * tid], b = g_tot[2 * tid + 1];
    int p = a + b;
    int v = p;
#pragma unroll
    for (int off = 1; off < 32; off <<= 1) {
        int u = __shfl_up_sync(0xffffffffu, v, off);
        if (lane >= off) v += u;
    }
    if (lane == 31) wsum[w] = v;
    __syncthreads();
    if (w == 0) {
        int s = wsum[lane];
        int t = s;
#pragma unroll
        for (int off = 1; off < 32; off <<= 1) {
            int u = __shfl_up_sync(0xffffffffu, t, off);
            if (lane >= off) t += u;
        }
        woff[lane] = t - s;
    }
    __syncthreads();
    int excl = woff[w] + (v - p);
    g_colptr[2 * tid]     = excl;
    g_colptr[2 * tid + 1] = excl + a;
    if (tid == 1023) g_colptr[Nn] = excl + p;
}

// Copy slot scratch -> g_rv at scanned offsets. Thread = (n, mc) slot.
__global__ void k3_compact() {
    const int idx = blockIdx.x * 256 + threadIdx.x;    // n*NCH + mc
    const int n = idx >> 7;
    const int cnt = g_cnt[idx];
    int off = g_colptr[n] + g_off2[idx];
    if (off + cnt > MAXNNZ) return;                    // safety guard
    const float2* sc = g_sc + (size_t)idx * 16;
    for (int i = 0; i < cnt; i++) g_rv[off + i] = sc[i];
}

// ---------------------------------------------------------------------------
// K4: block = column n. Phase A: cooperative weights (rv read direct, 8B
// broadcast per 16 threads) into smem. Phase B: warp bp streams entries
// (LDS.64 -> LDG wx -> 2 FFMA). Coalesced 256B store to g_yT[bp][n][*].
// 32.3KB smem + launch_bounds(512,4) -> 4 resident blocks/SM.
// ---------------------------------------------------------------------------
__global__ void __launch_bounds__(512, 4) k4_out() {
    __shared__ __align__(16) float2 s_w2[MAXE * BP];   // 32KB
    __shared__ __align__(16) float4 s_t1[BP];

    const int n = blockIdx.x;
    const int tid = threadIdx.x;
    const int bp = tid >> 5, lane = tid & 31;

    if (tid < BP) s_t1[tid] = g_T1n[n * BP + tid];
    __syncthreads();

    const int lo = g_colptr[n], hi = g_colptr[n + 1];
    const __half2* __restrict__ wxh = g_Wxh + (size_t)bp * Nn * (Ff / 2);
    const float4* __restrict__ t2tab = g_T2n;
    const float2* __restrict__ rv = g_rv;

    float a0 = 0.f, a1 = 0.f;

    for (int base = lo; base < hi; base += MAXE) {
        const int cnt = min(hi - base, MAXE);

        // Phase A: weights for all (j, bp) pairs; rv[base+j] broadcast-loaded.
        for (int idx = tid; idx < cnt * BP; idx += 512) {
            int j = idx >> 4, bpa = idx & 15;
            float2 e = rv[base + j];
            int mo = __float_as_int(e.x);
            float4 t2 = t2tab[(mo >> 1) | bpa];
            float4 t1 = s_t1[bpa];
            float t = t1.x + t2.x;
            float wgt = e.y * ((t >= 0.f) ? t1.y * t2.y : t1.z * t2.z);
            s_w2[idx] = make_float2(e.x, wgt);
        }
        __syncthreads();

        // Phase B: gather-accumulate per (bp-warp, f-pair-lane).
        const float2* wrow = s_w2 + bp;
#pragma unroll 4
        for (int j = 0; j < cnt; j++) {
            float2 mw = wrow[j * BP];
            int mo = __float_as_int(mw.x);
            float2 wx = __half22float2(wxh[mo + lane]);
            a0 = fmaf(mw.y, wx.x, a0);
            a1 = fmaf(mw.y, wx.y, a1);
        }
        __syncthreads();
    }

    float2* yt = (float2*)(g_yT + ((size_t)bp * Nn + n) * Ff);
    yt[lane] = make_float2(fmaxf(a0, 0.f), fmaxf(a1, 0.f));
}

// ---------------------------------------------------------------------------
// K5: transpose g_yT[bp][n][f] -> out[bp*64+f][n]. 32x32 padded-smem tiles.
// ---------------------------------------------------------------------------
__global__ void k5_transpose(float* __restrict__ out) {
    __shared__ float tile[32][33];
    const int bp = blockIdx.z;
    const int f0 = blockIdx.y * 32;
    const int n0 = blockIdx.x * 32;
    const int w = threadIdx.x >> 5, lane = threadIdx.x & 31;

    const float* src = g_yT + ((size_t)bp * Nn + n0) * Ff + f0;
#pragma unroll
    for (int k = 0; k < 4; k++) {
        int r = w + 8 * k;
        tile[r][lane] = src[(size_t)r * Ff + lane];
    }
    __syncthreads();

    float* dst = out + ((size_t)bp * Ff + f0) * Nn + n0;
#pragma unroll
    for (int k = 0; k < 4; k++) {
        int r = w + 8 * k;
        dst[(size_t)r * Nn + lane] = tile[lane][r];
    }
}

// ---------------------------------------------------------------------------
// Launch order: k3_compact at slot 4 (profiled). k1 has no deps -> slot 5.
// ---------------------------------------------------------------------------
extern "C" void kernel_launch(void* const* d_in, const int* in_sizes, int n_in,
                              void* d_out, int out_size) {
    const float* x = (const float*)d_in[0];
    const float* a = (const float*)d_in[1];
    const float* W = (const float*)d_in[2];
    const float* S = (const float*)d_in[3];
    float* out = (float*)d_out;

    k3_count<<<dim3(2, NCH), 256>>>(S);
    k3_offs<<<256, 256>>>();
    k3_scan<<<1, 1024>>>();
    k3_compact<<<Nn * NCH / 256, 256>>>();   // 4th launch -> profiled
    k1_wx<<<dim3(8, Pp, Bb), 256>>>(x, a, W);
    k2_rowstats<<<Nn, 256>>>(S);
    k4_out<<<Nn, 512>>>();
    k5_transpose<<<dim3(Nn / 32, Ff / 32, BP), 256>>>(out);
}

// round 15
// speedup vs baseline: 1.2260x; 1.2260x over previous
#include <cuda_runtime.h>
#include <cuda_fp16.h>
#include <math.h>

#define Bb 4
#define Gg 128
#define Nn 2048
#define Pp 4
#define Ff 64
#define BP 16
#define ZTOL 1e-9f
#define NCH 128
#define CHR 16
#define MAXNNZ (1 << 19)
#define MAXE 256

__device__ __align__(16) __half2 g_Wxh[BP * Nn * (Ff / 2)];
__device__ __align__(16) float4  g_T1n[Nn * BP + BP];
__device__ __align__(16) float4  g_T2n[Nn * BP];
__device__ float g_s2p[BP * Nn];
__device__ float g_s1q[4 * BP * Nn];                 // f-quarter partials
__device__ float g_s2q[4 * BP * Nn];
__device__ __align__(16) int g_cnt[Nn * NCH];
__device__ __align__(16) int g_off2[Nn * NCH];
__device__ int   g_tot[Nn];
__device__ int   g_colptr[Nn + 1];
__device__ __align__(16) float2 g_rv[MAXNNZ];
__device__ __align__(16) float  g_yT[BP * Nn * Ff];  // [bp][n][f] 8MB

// ---------------------------------------------------------------------------
// K1 (f-split x4): block = (fq, nchunk, p, b); computes 16 f's for 256 n's.
// 128 blocks -> ~128 SMs active (was 32). Emits fp16 Wx slice + s1/s2 partials.
// ---------------------------------------------------------------------------
__global__ void k1_wx(const float* __restrict__ x, const float* __restrict__ a,
                      const float* __restrict__ W) {
    const int bx = blockIdx.x;            // 0..31: fq = bx>>3, nch = bx&7
    const int fq = bx >> 3;
    const int b = blockIdx.z, p = blockIdx.y;
    const int n = (bx & 7) * 256 + threadIdx.x;

    __shared__ __align__(16) float Ws[Gg * 16];      // [g][16f] 8KB
    __shared__ float as1[16], as2[16];

    for (int i = threadIdx.x; i < Gg * 16; i += 256) {
        int fl = i >> 7, g = i & 127;
        Ws[g * 16 + fl] = W[(p * Ff + fq * 16 + fl) * Gg + g];
    }
    if (threadIdx.x < 16) {
        as1[threadIdx.x] = a[p * 2 * Ff + fq * 16 + threadIdx.x];
        as2[threadIdx.x] = a[p * 2 * Ff + Ff + fq * 16 + threadIdx.x];
    }
    __syncthreads();

    float4 acc[4];
#pragma unroll
    for (int i = 0; i < 4; i++) acc[i] = make_float4(0.f, 0.f, 0.f, 0.f);

    const float* xb = x + ((size_t)b * Gg) * Nn + n;
    const float4* Ws4 = (const float4*)Ws;

    for (int g = 0; g < Gg; g++) {
        float xv = xb[(size_t)g * Nn];
#pragma unroll
        for (int i = 0; i < 4; i++) {
            float4 w = Ws4[g * 4 + i];
            acc[i].x += w.x * xv; acc[i].y += w.y * xv;
            acc[i].z += w.z * xv; acc[i].w += w.w * xv;
        }
    }

    const int bp = b * Pp + p;
    __half2* dsth = g_Wxh + (size_t)(bp * Nn + n) * (Ff / 2) + fq * 8;
    float s1 = 0.f, s2 = 0.f;
#pragma unroll
    for (int i = 0; i < 4; i++) {
        dsth[2 * i]     = __floats2half2_rn(acc[i].x, acc[i].y);
        dsth[2 * i + 1] = __floats2half2_rn(acc[i].z, acc[i].w);
        s1 += as1[4*i+0]*acc[i].x + as1[4*i+1]*acc[i].y + as1[4*i+2]*acc[i].z + as1[4*i+3]*acc[i].w;
        s2 += as2[4*i+0]*acc[i].x + as2[4*i+1]*acc[i].y + as2[4*i+2]*acc[i].z + as2[4*i+3]*acc[i].w;
    }
    g_s1q[(fq * BP + bp) * Nn + n] = s1;
    g_s2q[(fq * BP + bp) * Nn + n] = s2;
}

// Sum the 4 f-quarter partials; emit s2 plane + T1 exp table.
__global__ void k1_reduce() {
    const int idx = blockIdx.x * 256 + threadIdx.x;  // bp*Nn + n
    float s1 = 0.f, s2 = 0.f;
#pragma unroll
    for (int q = 0; q < 4; q++) {
        s1 += g_s1q[q * BP * Nn + idx];
        s2 += g_s2q[q * BP * Nn + idx];
    }
    const int bp = idx >> 11, n = idx & (Nn - 1);
    g_s2p[idx] = s2;
    g_T1n[n * BP + bp] = make_float4(s1, __expf(s1), __expf(0.2f * s1), 0.f);
}

// ---------------------------------------------------------------------------
// K2: ballot-compressed denominators (MUFU-free hot loop via T1 table).
// ---------------------------------------------------------------------------
__global__ void k2_rowstats(const float* __restrict__ S) {
    const int m = blockIdx.x;
    const int tid = threadIdx.x;
    const int w = tid >> 5, lane = tid & 31;

    __shared__ float red[8][BP];

    const float s2l = g_s2p[(lane & 15) * Nn + m];
    const float eas = __expf(s2l);
    const float ebs = __expf(0.2f * s2l);
    float D = 0.f;
    const float4* row4 = (const float4*)(S + (size_t)m * Nn);

#pragma unroll
    for (int seg = 0; seg < 2; seg++) {
        const int base = (seg * 8 + w) * 128;
        float4 v = row4[base / 4 + lane];
        int dn = m - (base + 4 * lane);
        if (dn == 0) v.x += 1.f; else if (dn == 1) v.y += 1.f;
        else if (dn == 2) v.z += 1.f; else if (dn == 3) v.w += 1.f;
        unsigned bm[4];
        bm[0] = __ballot_sync(0xffffffffu, fabsf(v.x) > ZTOL);
        bm[1] = __ballot_sync(0xffffffffu, fabsf(v.y) > ZTOL);
        bm[2] = __ballot_sync(0xffffffffu, fabsf(v.z) > ZTOL);
        bm[3] = __ballot_sync(0xffffffffu, fabsf(v.w) > ZTOL);
#pragma unroll
        for (int k = 0; k < 4; k++) {
            unsigned msk = bm[k];
            while (msk) {
                int j = __ffs(msk) - 1;
                msk &= msk - 1;
                int ne = base + 4 * j + k;
                float4 t1 = g_T1n[ne * BP + lane];
                float t = s2l + t1.x;
                D += (t >= 0.f) ? eas * t1.y : ebs * t1.z;
            }
        }
    }

    if (lane < BP) red[w][lane] = D;
    __syncthreads();
    if (tid < BP) {
        float d = 0.f;
#pragma unroll
        for (int ww = 0; ww < 8; ww++) d += red[ww][tid];
        float ci = (d > 0.f) ? 1.f / d : 0.f;
        float s2 = g_s2p[tid * Nn + m];
        g_T2n[m * BP + tid] =
            make_float4(s2, __expf(s2) * ci, __expf(0.2f * s2) * ci, 0.f);
    }
}

// ---------------------------------------------------------------------------
// K3: deterministic CSC build (R13 form).
// ---------------------------------------------------------------------------
__global__ void k3_count(const float* __restrict__ S) {
    const int cg = blockIdx.x * 256 + threadIdx.x;
    const int n0 = cg * 4;
    const int mc = blockIdx.y, m0 = mc * CHR;
    int c0 = 0, c1 = 0, c2 = 0, c3 = 0;
#pragma unroll
    for (int mm = 0; mm < CHR; mm++) {
        float4 v = *(const float4*)(S + (size_t)(m0 + mm) * Nn + n0);
        if (fabsf(v.x) > ZTOL) c0++;
        if (fabsf(v.y) > ZTOL) c1++;
        if (fabsf(v.z) > ZTOL) c2++;
        if (fabsf(v.w) > ZTOL) c3++;
    }
    g_cnt[(n0 + 0) * NCH + mc] = c0;
    g_cnt[(n0 + 1) * NCH + mc] = c1;
    g_cnt[(n0 + 2) * NCH + mc] = c2;
    g_cnt[(n0 + 3) * NCH + mc] = c3;
}

__global__ void k3_offs() {
    const int n = blockIdx.x * 8 + (threadIdx.x >> 5);
    const int lane = threadIdx.x & 31;
    int4 c = *(const int4*)&g_cnt[n * NCH + 4 * lane];
    int s = c.x + c.y + c.z + c.w;
    int v = s;
#pragma unroll
    for (int off = 1; off < 32; off <<= 1) {
        int u = __shfl_up_sync(0xffffffffu, v, off);
        if (lane >= off) v += u;
    }
    int e = v - s;
    *(int4*)&g_off2[n * NCH + 4 * lane] =
        make_int4(e, e + c.x, e + c.x + c.y, e + c.x + c.y + c.z);
    if (lane == 31) g_tot[n] = v;
}

__global__ void k3_scan() {
    __shared__ int wsum[32];
    __shared__ int woff[32];
    const int tid = threadIdx.x;
    const int w = tid >> 5, lane = tid & 31;
    int a = g_tot[2 * tid], b = g_tot[2 * tid + 1];
    int p = a + b;
    int v = p;
#pragma unroll
    for (int off = 1; off < 32; off <<= 1) {
        int u = __shfl_up_sync(0xffffffffu, v, off);
        if (lane >= off) v += u;
    }
    if (lane == 31) wsum[w] = v;
    __syncthreads();
    if (w == 0) {
        int s = wsum[lane];
        int t = s;
#pragma unroll
        for (int off = 1; off < 32; off <<= 1) {
            int u = __shfl_up_sync(0xffffffffu, t, off);
            if (lane >= off) t += u;
        }
        woff[lane] = t - s;
    }
    __syncthreads();
    int excl = woff[w] + (v - p);
    g_colptr[2 * tid]     = excl;
    g_colptr[2 * tid + 1] = excl + a;
    if (tid == 1023) g_colptr[Nn] = excl + p;
}

__global__ void k3_fill(const float* __restrict__ S) {
    const int cg = blockIdx.x * 256 + threadIdx.x;
    const int n0 = cg * 4;
    const int mc = blockIdx.y, m0 = mc * CHR;
    int o0 = g_colptr[n0 + 0] + g_off2[(n0 + 0) * NCH + mc];
    int o1 = g_colptr[n0 + 1] + g_off2[(n0 + 1) * NCH + mc];
    int o2 = g_colptr[n0 + 2] + g_off2[(n0 + 2) * NCH + mc];
    int o3 = g_colptr[n0 + 3] + g_off2[(n0 + 3) * NCH + mc];
#pragma unroll
    for (int mm = 0; mm < CHR; mm++) {
        const int m = m0 + mm;
        float4 v = *(const float4*)(S + (size_t)m * Nn + n0);
        float mo = __int_as_float(m * (Ff / 2));
        if (fabsf(v.x) > ZTOL && o0 < MAXNNZ) g_rv[o0++] = make_float2(mo, v.x);
        if (fabsf(v.y) > ZTOL && o1 < MAXNNZ) g_rv[o1++] = make_float2(mo, v.y);
        if (fabsf(v.z) > ZTOL && o2 < MAXNNZ) g_rv[o2++] = make_float2(mo, v.z);
        if (fabsf(v.w) > ZTOL && o3 < MAXNNZ) g_rv[o3++] = make_float2(mo, v.w);
    }
}

// ---------------------------------------------------------------------------
// K4 (R13 proven structure; Phase B unroll 8): block = column n.
// Phase A: cooperative weights into smem. Phase B: warp bp streams entries.
// Coalesced 256B store to g_yT[bp][n][*].
// ---------------------------------------------------------------------------
__global__ void __launch_bounds__(512) k4_out() {
    __shared__ __align__(16) float2 s_rv[MAXE];
    __shared__ __align__(16) float2 s_w2[MAXE * BP];
    __shared__ __align__(16) float4 s_t1[BP];

    const int n = blockIdx.x;
    const int tid = threadIdx.x;
    const int bp = tid >> 5, lane = tid & 31;

    if (tid < BP) s_t1[tid] = g_T1n[n * BP + tid];

    const int lo = g_colptr[n], hi = g_colptr[n + 1];
    const __half2* __restrict__ wxh = g_Wxh + (size_t)bp * Nn * (Ff / 2);
    const float4* __restrict__ t2tab = g_T2n;
    const float2* __restrict__ rv = g_rv;

    float a0 = 0.f, a1 = 0.f;

    for (int base = lo; base < hi; base += MAXE) {
        const int cnt = min(hi - base, MAXE);
        if (tid < cnt) s_rv[tid] = rv[base + tid];
        __syncthreads();

        for (int idx = tid; idx < cnt * BP; idx += 512) {
            int j = idx >> 4, bpa = idx & 15;
            float2 e = s_rv[j];
            int mo = __float_as_int(e.x);
            float4 t2 = t2tab[(mo >> 1) | bpa];
            float4 t1 = s_t1[bpa];
            float t = t1.x + t2.x;
            float wgt = e.y * ((t >= 0.f) ? t1.y * t2.y : t1.z * t2.z);
            s_w2[idx] = make_float2(e.x, wgt);
        }
        __syncthreads();

        const float2* wrow = s_w2 + bp;
#pragma unroll 8
        for (int j = 0; j < cnt; j++) {
            float2 mw = wrow[j * BP];
            int mo = __float_as_int(mw.x);
            float2 wx = __half22float2(wxh[mo + lane]);
            a0 = fmaf(mw.y, wx.x, a0);
            a1 = fmaf(mw.y, wx.y, a1);
        }
        __syncthreads();
    }

    float2* yt = (float2*)(g_yT + ((size_t)bp * Nn + n) * Ff);
    yt[lane] = make_float2(fmaxf(a0, 0.f), fmaxf(a1, 0.f));
}

// ---------------------------------------------------------------------------
// K5: transpose g_yT[bp][n][f] -> out[bp*64+f][n]. 32x32 padded-smem tiles.
// ---------------------------------------------------------------------------
__global__ void k5_transpose(float* __restrict__ out) {
    __shared__ float tile[32][33];
    const int bp = blockIdx.z;
    const int f0 = blockIdx.y * 32;
    const int n0 = blockIdx.x * 32;
    const int w = threadIdx.x >> 5, lane = threadIdx.x & 31;

    const float* src = g_yT + ((size_t)bp * Nn + n0) * Ff + f0;
#pragma unroll
    for (int k = 0; k < 4; k++) {
        int r = w + 8 * k;
        tile[r][lane] = src[(size_t)r * Ff + lane];
    }
    __syncthreads();

    float* dst = out + ((size_t)bp * Ff + f0) * Nn + n0;
#pragma unroll
    for (int k = 0; k < 4; k++) {
        int r = w + 8 * k;
        dst[(size_t)r * Nn + lane] = tile[lane][r];
    }
}

// ---------------------------------------------------------------------------
// Launch order: new k1_wx at profiled slot 4.
// ---------------------------------------------------------------------------
extern "C" void kernel_launch(void* const* d_in, const int* in_sizes, int n_in,
                              void* d_out, int out_size) {
    const float* x = (const float*)d_in[0];
    const float* a = (const float*)d_in[1];
    const float* W = (const float*)d_in[2];
    const float* S = (const float*)d_in[3];
    float* out = (float*)d_out;

    k3_count<<<dim3(2, NCH), 256>>>(S);
    k3_offs<<<256, 256>>>();
    k3_scan<<<1, 1024>>>();
    k1_wx<<<dim3(32, Pp, Bb), 256>>>(x, a, W);   // 4th launch -> profiled
    k1_reduce<<<BP * Nn / 256, 256>>>();
    k3_fill<<<dim3(2, NCH), 256>>>(S);
    k2_rowstats<<<Nn, 256>>>(S);
    k4_out<<<Nn, 512>>>();
    k5_transpose<<<dim3(Nn / 32, Ff / 32, BP), 256>>>(out);
}